// round 1
// baseline (speedup 1.0000x reference)
#include <cuda_runtime.h>

// Problem dims (fixed by the dataset)
#define M_TOK  8192   // tokens (rows of x / out)
#define N_OUT  4096   // d_out
#define K_IN   4096   // d_in
#define R_LORA 16

// Scratch for t = x @ A^T  [M_TOK, R_LORA]  (512 KB, static device global — no runtime alloc)
__device__ float g_t[M_TOK * R_LORA];

// ---------------------------------------------------------------------------
// Kernel 1: t[n][r] = sum_k x[n][k] * A[r][k]
// One block per token, 16 warps, warp w computes r=w via coalesced float4 dot.
// ---------------------------------------------------------------------------
__global__ __launch_bounds__(512) void lora_xA_kernel(
    const float* __restrict__ x, const float* __restrict__ A)
{
    const int n    = blockIdx.x;
    const int wid  = threadIdx.x >> 5;   // 0..15 = r
    const int lane = threadIdx.x & 31;

    const float* __restrict__ xr = x + (size_t)n   * K_IN;
    const float* __restrict__ ar = A + (size_t)wid * K_IN;

    float acc = 0.0f;
    for (int k = lane * 4; k < K_IN; k += 32 * 4) {
        float4 xv = *(const float4*)(xr + k);
        float4 av = *(const float4*)(ar + k);
        acc += xv.x * av.x + xv.y * av.y + xv.z * av.z + xv.w * av.w;
    }
    #pragma unroll
    for (int off = 16; off; off >>= 1)
        acc += __shfl_xor_sync(0xffffffffu, acc, off);

    if (lane == 0) g_t[n * R_LORA + wid] = acc;
}

// ---------------------------------------------------------------------------
// Kernel 2: main GEMM  out[m][n] = x[m,:]·W[n,:] + bias[n] + s * t[m,:]·B[n,:]
// 128x128 block tile, BK=16, 256 threads, 8x8 per thread, fp32 FFMA.
// ---------------------------------------------------------------------------
#define BM 128
#define BN 128
#define BK 16
#define TM 8
#define TN 8

__global__ __launch_bounds__(256) void lora_gemm_kernel(
    const float* __restrict__ x,
    const float* __restrict__ W,
    const float* __restrict__ bias,
    const float* __restrict__ lora_B,
    const float* __restrict__ lora_scale_p,
    float* __restrict__ out)
{
    __shared__ float As[BK][BM];   // x tile, transposed to k-major
    __shared__ float Bs[BK][BN];   // W tile, transposed to k-major

    const int bm  = blockIdx.y * BM;
    const int bn  = blockIdx.x * BN;
    const int tid = threadIdx.x;

    const int tx = tid & 15;   // n direction (0..15)
    const int ty = tid >> 4;   // m direction (0..15)

    // tile-load mapping: 512 float4 per operand tile / 256 threads = 2 each
    const int lrow = tid >> 2;      // 0..63
    const int lc4  = tid & 3;       // 0..3 (which float4 along k)

    float acc[TM][TN];
    #pragma unroll
    for (int i = 0; i < TM; i++)
        #pragma unroll
        for (int j = 0; j < TN; j++)
            acc[i][j] = 0.0f;

    for (int k0 = 0; k0 < K_IN; k0 += BK) {
        #pragma unroll
        for (int h = 0; h < 2; h++) {
            const int row = lrow + h * 64;
            float4 v = *(const float4*)(x + (size_t)(bm + row) * K_IN + k0 + lc4 * 4);
            As[lc4 * 4 + 0][row] = v.x;
            As[lc4 * 4 + 1][row] = v.y;
            As[lc4 * 4 + 2][row] = v.z;
            As[lc4 * 4 + 3][row] = v.w;
        }
        #pragma unroll
        for (int h = 0; h < 2; h++) {
            const int row = lrow + h * 64;
            float4 v = *(const float4*)(W + (size_t)(bn + row) * K_IN + k0 + lc4 * 4);
            Bs[lc4 * 4 + 0][row] = v.x;
            Bs[lc4 * 4 + 1][row] = v.y;
            Bs[lc4 * 4 + 2][row] = v.z;
            Bs[lc4 * 4 + 3][row] = v.w;
        }
        __syncthreads();

        #pragma unroll
        for (int k = 0; k < BK; k++) {
            float4 a0 = *(const float4*)&As[k][ty * TM];
            float4 a1 = *(const float4*)&As[k][ty * TM + 4];
            float4 b0 = *(const float4*)&Bs[k][tx * TN];
            float4 b1 = *(const float4*)&Bs[k][tx * TN + 4];
            float a[TM] = {a0.x, a0.y, a0.z, a0.w, a1.x, a1.y, a1.z, a1.w};
            float b[TN] = {b0.x, b0.y, b0.z, b0.w, b1.x, b1.y, b1.z, b1.w};
            #pragma unroll
            for (int i = 0; i < TM; i++)
                #pragma unroll
                for (int j = 0; j < TN; j++)
                    acc[i][j] += a[i] * b[j];
        }
        __syncthreads();
    }

    // ---- Epilogue: bias + LoRA correction ----
    // Reuse smem: Ts[128][16] = t rows for this m-block, Bl[128][16] = lora_B
    // rows for this n-block. (BK*BM floats == 128*16 floats, exact fit.)
    float* Ts = &As[0][0];
    float* Bl = &Bs[0][0];
    #pragma unroll
    for (int h = 0; h < 2; h++) {
        const int idx = tid + h * 256;      // 0..511
        const int row = idx >> 2;           // 0..127
        const int c4  = idx & 3;
        *(float4*)(Ts + row * R_LORA + c4 * 4) =
            *(const float4*)(g_t + (size_t)(bm + row) * R_LORA + c4 * 4);
        *(float4*)(Bl + row * R_LORA + c4 * 4) =
            *(const float4*)(lora_B + (size_t)(bn + row) * R_LORA + c4 * 4);
    }
    __syncthreads();

    const float s = *lora_scale_p;

    float bq[TN];
    #pragma unroll
    for (int j = 0; j < TN; j++)
        bq[j] = bias[bn + tx * TN + j];

    #pragma unroll
    for (int i = 0; i < TM; i++) {
        const int m = ty * TM + i;
        float tv[R_LORA];
        #pragma unroll
        for (int r = 0; r < R_LORA; r += 4) {
            float4 v = *(const float4*)(Ts + m * R_LORA + r);
            tv[r + 0] = v.x; tv[r + 1] = v.y; tv[r + 2] = v.z; tv[r + 3] = v.w;
        }
        float vals[TN];
        #pragma unroll
        for (int j = 0; j < TN; j++) {
            const int n = tx * TN + j;
            float lor = 0.0f;
            #pragma unroll
            for (int r = 0; r < R_LORA; r += 4) {
                float4 bv = *(const float4*)(Bl + n * R_LORA + r);
                lor += tv[r + 0] * bv.x + tv[r + 1] * bv.y
                     + tv[r + 2] * bv.z + tv[r + 3] * bv.w;
            }
            vals[j] = acc[i][j] + bq[j] + s * lor;
        }
        float* orow = out + (size_t)(bm + m) * N_OUT + bn + tx * TN;
        *(float4*)(orow + 0) = make_float4(vals[0], vals[1], vals[2], vals[3]);
        *(float4*)(orow + 4) = make_float4(vals[4], vals[5], vals[6], vals[7]);
    }
}

// ---------------------------------------------------------------------------
// Launch
// Inputs (metadata order): x, W, bias, lora_B, lora_A, lora_scale
// ---------------------------------------------------------------------------
extern "C" void kernel_launch(void* const* d_in, const int* in_sizes, int n_in,
                              void* d_out, int out_size)
{
    const float* x     = (const float*)d_in[0];
    const float* W     = (const float*)d_in[1];
    const float* bias  = (const float*)d_in[2];
    const float* loraB = (const float*)d_in[3];
    const float* loraA = (const float*)d_in[4];
    const float* scale = (const float*)d_in[5];   // device scalar — read in-kernel
    float* out = (float*)d_out;

    lora_xA_kernel<<<M_TOK, 512>>>(x, loraA);

    dim3 grid(N_OUT / BN, M_TOK / BM);   // (32, 64)
    lora_gemm_kernel<<<grid, 256>>>(x, W, bias, loraB, scale, out);
}

// round 4
// speedup vs baseline: 3.0411x; 3.0411x over previous
#include <cuda_runtime.h>
#include <cuda_bf16.h>
#include <cstdint>

#define M_TOK 8192
#define N_OUT 4096
#define K_IN  4096
#define K3    (3 * K_IN)          // 12288: [hi | hi | lo] x [hi | lo | hi]

#define BM 128
#define BN 128
#define BK 64
#define NCHUNK (K3 / BK)          // 192
#define NSTAGE 4
#define STAGE_BYTES 32768         // A 16K + B 16K (bf16 128x64 each)
#define SMEM_TOTAL (NSTAGE * STAGE_BYTES)   // 131072

// -------------------- static device scratch (288 MB) --------------------
__device__ __nv_bfloat16 g_ax[(size_t)M_TOK * K3];
__device__ __nv_bfloat16 g_bw[(size_t)N_OUT * K3];

// -------------------- helpers --------------------
static __device__ __forceinline__ uint32_t s2u(const void* p) {
    uint32_t a;
    asm("{ .reg .u64 t; cvta.to.shared.u64 t, %1; cvt.u32.u64 %0, t; }"
        : "=r"(a) : "l"(p));
    return a;
}
#define SWZ(o) ((o) ^ (((o) >> 3) & 0x70))

static __device__ __forceinline__ void cp16(uint32_t dst, const void* src) {
    asm volatile("cp.async.cg.shared.global [%0], [%1], 16;" :: "r"(dst), "l"(src));
}
static __device__ __forceinline__ void cp_commit() {
    asm volatile("cp.async.commit_group;" ::: "memory");
}

static __device__ __forceinline__ void ldmx4(uint32_t* r, uint32_t addr) {
    asm volatile("ldmatrix.sync.aligned.m8n8.x4.shared.b16 {%0,%1,%2,%3}, [%4];"
                 : "=r"(r[0]), "=r"(r[1]), "=r"(r[2]), "=r"(r[3]) : "r"(addr));
}
static __device__ __forceinline__ void mma16816(float* c, const uint32_t* a,
                                                uint32_t b0, uint32_t b1) {
    asm volatile(
        "mma.sync.aligned.m16n8k16.row.col.f32.bf16.bf16.f32 "
        "{%0,%1,%2,%3}, {%4,%5,%6,%7}, {%8,%9}, {%0,%1,%2,%3};"
        : "+f"(c[0]), "+f"(c[1]), "+f"(c[2]), "+f"(c[3])
        : "r"(a[0]), "r"(a[1]), "r"(a[2]), "r"(a[3]), "r"(b0), "r"(b1));
}

static __device__ __forceinline__ void split1(float v, unsigned short& h, unsigned short& l) {
    __nv_bfloat16 hb = __float2bfloat16(v);
    float r = v - __bfloat162float(hb);
    __nv_bfloat16 lb = __float2bfloat16(r);
    h = __bfloat16_as_ushort(hb);
    l = __bfloat16_as_ushort(lb);
}

// ---------- prepass 1: x -> g_ax rows [xh | xh | xl] ----------
__global__ __launch_bounds__(256) void pack_x(const float* __restrict__ x) {
    size_t idx4 = (size_t)blockIdx.x * 256 + threadIdx.x;
    int row = (int)(idx4 >> 10);          // 1024 float4 per 4096-row
    int col = (int)(idx4 & 1023) * 4;
    float4 v = *(const float4*)(x + (size_t)row * K_IN + col);
    ushort4 h, l;
    split1(v.x, h.x, l.x); split1(v.y, h.y, l.y);
    split1(v.z, h.z, l.z); split1(v.w, h.w, l.w);
    unsigned short* base = (unsigned short*)g_ax + (size_t)row * K3 + col;
    *(ushort4*)(base)            = h;
    *(ushort4*)(base + K_IN)     = h;
    *(ushort4*)(base + 2 * K_IN) = l;
}

// ---------- prepass 2: Wf = W + s*B@A -> g_bw rows [wh | wl | wh] ----------
__global__ __launch_bounds__(256) void pack_w(
    const float* __restrict__ W, const float* __restrict__ B,
    const float* __restrict__ A, const float* __restrict__ sp)
{
    size_t idx4 = (size_t)blockIdx.x * 256 + threadIdx.x;
    int row = (int)(idx4 >> 10);
    int col = (int)(idx4 & 1023) * 4;
    float s = *sp;

    float4 w = *(const float4*)(W + (size_t)row * K_IN + col);
    float4 acc = make_float4(0.f, 0.f, 0.f, 0.f);
    const float* brow = B + (size_t)row * 16;
    #pragma unroll
    for (int r = 0; r < 16; r++) {
        float b = brow[r];
        float4 a = *(const float4*)(A + (size_t)r * K_IN + col);
        acc.x += b * a.x; acc.y += b * a.y; acc.z += b * a.z; acc.w += b * a.w;
    }
    w.x += s * acc.x; w.y += s * acc.y; w.z += s * acc.z; w.w += s * acc.w;

    ushort4 h, l;
    split1(w.x, h.x, l.x); split1(w.y, h.y, l.y);
    split1(w.z, h.z, l.z); split1(w.w, h.w, l.w);
    unsigned short* base = (unsigned short*)g_bw + (size_t)row * K3 + col;
    *(ushort4*)(base)            = h;
    *(ushort4*)(base + K_IN)     = l;
    *(ushort4*)(base + 2 * K_IN) = h;
}

// -------------------- main GEMM: out = A' @ B'^T + bias --------------------
__global__ __launch_bounds__(256, 1) void lora_mma_gemm(
    const float* __restrict__ bias, float* __restrict__ out)
{
    extern __shared__ __align__(1024) char smem[];
    const uint32_t sb = s2u(smem);
    const int tid  = threadIdx.x;
    const int lane = tid & 31;
    const int wid  = tid >> 5;
    const int warp_m = wid & 1;       // 2 warps in M -> 64 rows each
    const int warp_n = wid >> 1;      // 4 warps in N -> 32 cols each
    const int bm = blockIdx.y * BM;
    const int bn = blockIdx.x * BN;

    const __nv_bfloat16* Ag = g_ax + (size_t)bm * K3;
    const __nv_bfloat16* Bg = g_bw + (size_t)bn * K3;

    // fragment address components (ldmatrix lane mapping, A and B identical)
    const int lrow = lane & 15;
    const int lkb  = (lane >> 4) * 16;   // byte offset along k

    float c[4][4][4];
    #pragma unroll
    for (int i = 0; i < 4; i++)
        #pragma unroll
        for (int j = 0; j < 4; j++)
            #pragma unroll
            for (int q = 0; q < 4; q++) c[i][j][q] = 0.f;

    auto load_stage = [&](int ch, int st) {
        const uint32_t ab = sb + st * STAGE_BYTES;
        const uint32_t bb = ab + 16384;
        const int k0 = ch * BK;
        #pragma unroll
        for (int i = 0; i < 4; i++) {       // A: 1024 granules of 16B
            int G = tid + i * 256;
            int r = G >> 3, g = G & 7;
            cp16(ab + SWZ((uint32_t)(r * 128 + g * 16)),
                 Ag + (size_t)r * K3 + k0 + g * 8);
        }
        #pragma unroll
        for (int i = 0; i < 4; i++) {       // B: 1024 granules
            int G = tid + i * 256;
            int r = G >> 3, g = G & 7;
            cp16(bb + SWZ((uint32_t)(r * 128 + g * 16)),
                 Bg + (size_t)r * K3 + k0 + g * 8);
        }
        cp_commit();
    };

    #pragma unroll
    for (int s = 0; s < NSTAGE - 1; s++) load_stage(s, s);

    for (int ch = 0; ch < NCHUNK; ch++) {
        asm volatile("cp.async.wait_group 2;" ::: "memory");
        __syncthreads();

        const int st = ch & 3;
        const uint32_t ab = sb + st * STAGE_BYTES;
        const uint32_t bb = ab + 16384;

        #pragma unroll
        for (int ks = 0; ks < 4; ks++) {
            uint32_t ra[4][4], rb[2][4];
            #pragma unroll
            for (int mf = 0; mf < 4; mf++)
                ldmx4(ra[mf], ab + SWZ((uint32_t)((warp_m * 64 + mf * 16 + lrow) * 128
                                                  + ks * 32 + lkb)));
            #pragma unroll
            for (int nf2 = 0; nf2 < 2; nf2++)
                ldmx4(rb[nf2], bb + SWZ((uint32_t)((warp_n * 32 + nf2 * 16 + lrow) * 128
                                                   + ks * 32 + lkb)));
            #pragma unroll
            for (int mf = 0; mf < 4; mf++)
                #pragma unroll
                for (int nf = 0; nf < 4; nf++)
                    mma16816(c[mf][nf], ra[mf],
                             rb[nf >> 1][nf & 1], rb[nf >> 1][(nf & 1) + 2]);
        }
        __syncthreads();
        if (ch + NSTAGE - 1 < NCHUNK) load_stage(ch + NSTAGE - 1, (ch + NSTAGE - 1) & 3);
        else cp_commit();   // keep group accounting balanced
    }

    // -------- epilogue: regs + bias -> gmem --------
    const int tq = lane >> 2, t4 = lane & 3;
    float2 bv[4];
    #pragma unroll
    for (int nf = 0; nf < 4; nf++)
        bv[nf] = *(const float2*)(bias + bn + warp_n * 32 + nf * 8 + t4 * 2);

    #pragma unroll
    for (int mf = 0; mf < 4; mf++) {
        const int r0 = bm + warp_m * 64 + mf * 16 + tq;
        float* o0 = out + (size_t)r0 * N_OUT + bn + warp_n * 32;
        float* o1 = o0 + 8 * N_OUT;
        #pragma unroll
        for (int nf = 0; nf < 4; nf++) {
            const int colo = nf * 8 + t4 * 2;
            *(float2*)(o0 + colo) = make_float2(c[mf][nf][0] + bv[nf].x,
                                                c[mf][nf][1] + bv[nf].y);
            *(float2*)(o1 + colo) = make_float2(c[mf][nf][2] + bv[nf].x,
                                                c[mf][nf][3] + bv[nf].y);
        }
    }
}

// -------------------- launch --------------------
extern "C" void kernel_launch(void* const* d_in, const int* in_sizes, int n_in,
                              void* d_out, int out_size)
{
    (void)in_sizes; (void)n_in; (void)out_size;
    const float* x     = (const float*)d_in[0];
    const float* W     = (const float*)d_in[1];
    const float* bias  = (const float*)d_in[2];
    const float* loraB = (const float*)d_in[3];
    const float* loraA = (const float*)d_in[4];
    const float* scale = (const float*)d_in[5];
    float* out = (float*)d_out;

    pack_x<<<(int)((size_t)M_TOK * K_IN / 1024), 256>>>(x);
    pack_w<<<(int)((size_t)N_OUT * K_IN / 1024), 256>>>(W, loraB, loraA, scale);

    cudaFuncSetAttribute(lora_mma_gemm,
                         cudaFuncAttributeMaxDynamicSharedMemorySize, SMEM_TOTAL);
    dim3 grid(N_OUT / BN, M_TOK / BM);   // (32, 64)
    lora_mma_gemm<<<grid, 256, SMEM_TOTAL>>>(bias, out);
}

// round 7
// speedup vs baseline: 3.2983x; 1.0846x over previous
#include <cuda_runtime.h>
#include <cuda_bf16.h>
#include <cstdint>

#define M_TOK 8192
#define N_OUT 4096
#define K_IN  4096
#define K3    (3 * K_IN)          // 12288: [hi | hi | lo] x [hi | lo | hi]

#define BM 256
#define BN 128
#define BK 64
#define NCHUNK (K3 / BK)          // 192
#define NSTAGE 4
#define A_BYTES (BM * BK * 2)     // 32768
#define B_BYTES (BN * BK * 2)     // 16384
#define STAGE_BYTES (A_BYTES + B_BYTES)        // 49152
#define SMEM_TOTAL (NSTAGE * STAGE_BYTES)      // 196608

#define GRID_M (M_TOK / BM)       // 32
#define GRID_N (N_OUT / BN)       // 32
#define GROUP_M 8

// -------------------- static device scratch (288 MB) --------------------
__device__ __nv_bfloat16 g_ax[(size_t)M_TOK * K3];
__device__ __nv_bfloat16 g_bw[(size_t)N_OUT * K3];

// -------------------- helpers --------------------
static __device__ __forceinline__ uint32_t s2u(const void* p) {
    uint32_t a;
    asm("{ .reg .u64 t; cvta.to.shared.u64 t, %1; cvt.u32.u64 %0, t; }"
        : "=r"(a) : "l"(p));
    return a;
}
#define SWZ(o) ((o) ^ (((o) >> 3) & 0x70))

static __device__ __forceinline__ void cp16(uint32_t dst, const void* src) {
    asm volatile("cp.async.cg.shared.global [%0], [%1], 16;" :: "r"(dst), "l"(src));
}
static __device__ __forceinline__ void cp_commit() {
    asm volatile("cp.async.commit_group;" ::: "memory");
}

static __device__ __forceinline__ void ldmx4(uint32_t* r, uint32_t addr) {
    asm volatile("ldmatrix.sync.aligned.m8n8.x4.shared.b16 {%0,%1,%2,%3}, [%4];"
                 : "=r"(r[0]), "=r"(r[1]), "=r"(r[2]), "=r"(r[3]) : "r"(addr));
}
static __device__ __forceinline__ void mma16816(float* c, const uint32_t* a,
                                                uint32_t b0, uint32_t b1) {
    asm volatile(
        "mma.sync.aligned.m16n8k16.row.col.f32.bf16.bf16.f32 "
        "{%0,%1,%2,%3}, {%4,%5,%6,%7}, {%8,%9}, {%0,%1,%2,%3};"
        : "+f"(c[0]), "+f"(c[1]), "+f"(c[2]), "+f"(c[3])
        : "r"(a[0]), "r"(a[1]), "r"(a[2]), "r"(a[3]), "r"(b0), "r"(b1));
}

static __device__ __forceinline__ void split1(float v, unsigned short& h, unsigned short& l) {
    __nv_bfloat16 hb = __float2bfloat16(v);
    float r = v - __bfloat162float(hb);
    __nv_bfloat16 lb = __float2bfloat16(r);
    h = __bfloat16_as_ushort(hb);
    l = __bfloat16_as_ushort(lb);
}

// ---------- prepass 1: x -> g_ax rows [xh | xh | xl] ----------
__global__ __launch_bounds__(256) void pack_x(const float* __restrict__ x) {
    size_t idx4 = (size_t)blockIdx.x * 256 + threadIdx.x;
    int row = (int)(idx4 >> 10);
    int col = (int)(idx4 & 1023) * 4;
    float4 v = *(const float4*)(x + (size_t)row * K_IN + col);
    ushort4 h, l;
    split1(v.x, h.x, l.x); split1(v.y, h.y, l.y);
    split1(v.z, h.z, l.z); split1(v.w, h.w, l.w);
    unsigned short* base = (unsigned short*)g_ax + (size_t)row * K3 + col;
    *(ushort4*)(base)            = h;
    *(ushort4*)(base + K_IN)     = h;
    *(ushort4*)(base + 2 * K_IN) = l;
}

// ---------- prepass 2: Wf = W + s*B@A -> g_bw rows [wh | wl | wh] ----------
__global__ __launch_bounds__(256) void pack_w(
    const float* __restrict__ W, const float* __restrict__ B,
    const float* __restrict__ A, const float* __restrict__ sp)
{
    size_t idx4 = (size_t)blockIdx.x * 256 + threadIdx.x;
    int row = (int)(idx4 >> 10);
    int col = (int)(idx4 & 1023) * 4;
    float s = *sp;

    float4 w = *(const float4*)(W + (size_t)row * K_IN + col);
    float4 acc = make_float4(0.f, 0.f, 0.f, 0.f);
    const float* brow = B + (size_t)row * 16;
    #pragma unroll
    for (int r = 0; r < 16; r++) {
        float b = brow[r];
        float4 a = *(const float4*)(A + (size_t)r * K_IN + col);
        acc.x += b * a.x; acc.y += b * a.y; acc.z += b * a.z; acc.w += b * a.w;
    }
    w.x += s * acc.x; w.y += s * acc.y; w.z += s * acc.z; w.w += s * acc.w;

    ushort4 h, l;
    split1(w.x, h.x, l.x); split1(w.y, h.y, l.y);
    split1(w.z, h.z, l.z); split1(w.w, h.w, l.w);
    unsigned short* base = (unsigned short*)g_bw + (size_t)row * K3 + col;
    *(ushort4*)(base)            = h;
    *(ushort4*)(base + K_IN)     = l;
    *(ushort4*)(base + 2 * K_IN) = h;
}

// -------------------- main GEMM: out = A' @ B'^T + bias --------------------
__global__ __launch_bounds__(256, 1) void lora_mma_gemm(
    const float* __restrict__ bias, float* __restrict__ out)
{
    extern __shared__ __align__(1024) char smem[];
    const uint32_t sb = s2u(smem);
    const int tid  = threadIdx.x;
    const int lane = tid & 31;
    const int wid  = tid >> 5;
    const int warp_m = wid & 3;       // 4 warps in M -> 64 rows each
    const int warp_n = wid >> 2;      // 2 warps in N -> 64 cols each

    // grouped rasterization: 8 m-blocks per group, sweep n within group
    const int bid      = blockIdx.x;
    const int group    = bid / (GROUP_M * GRID_N);
    const int inner    = bid % (GROUP_M * GRID_N);
    const int bm       = (group * GROUP_M + (inner % GROUP_M)) * BM;
    const int bn       = (inner / GROUP_M) * BN;

    const __nv_bfloat16* Ag = g_ax + (size_t)bm * K3;
    const __nv_bfloat16* Bg = g_bw + (size_t)bn * K3;

    const int lrow = lane & 15;
    const int lkb  = (lane >> 4) * 16;

    float c[4][8][4];
    #pragma unroll
    for (int i = 0; i < 4; i++)
        #pragma unroll
        for (int j = 0; j < 8; j++)
            #pragma unroll
            for (int q = 0; q < 4; q++) c[i][j][q] = 0.f;

    auto load_stage = [&](int ch, int st) {
        const uint32_t ab = sb + st * STAGE_BYTES;
        const uint32_t bb = ab + A_BYTES;
        const int k0 = ch * BK;
        #pragma unroll
        for (int i = 0; i < 8; i++) {       // A: 2048 granules of 16B
            int G = tid + i * 256;
            int r = G >> 3, g = G & 7;
            cp16(ab + SWZ((uint32_t)(r * 128 + g * 16)),
                 Ag + (size_t)r * K3 + k0 + g * 8);
        }
        #pragma unroll
        for (int i = 0; i < 4; i++) {       // B: 1024 granules
            int G = tid + i * 256;
            int r = G >> 3, g = G & 7;
            cp16(bb + SWZ((uint32_t)(r * 128 + g * 16)),
                 Bg + (size_t)r * K3 + k0 + g * 8);
        }
        cp_commit();
    };

    #pragma unroll
    for (int s = 0; s < NSTAGE - 1; s++) load_stage(s, s);

    for (int ch = 0; ch < NCHUNK; ch++) {
        asm volatile("cp.async.wait_group 2;" ::: "memory");
        __syncthreads();

        // issue loads for stage ch+3 (reuses slot (ch+3)&3 == (ch-1)&3, whose
        // reads completed in iteration ch-1 before the barrier above)
        if (ch + NSTAGE - 1 < NCHUNK) load_stage(ch + NSTAGE - 1, (ch + NSTAGE - 1) & 3);
        else cp_commit();   // keep group accounting balanced

        const int st = ch & 3;
        const uint32_t ab = sb + st * STAGE_BYTES;
        const uint32_t bb = ab + A_BYTES;

        #pragma unroll
        for (int ks = 0; ks < 4; ks++) {
            uint32_t ra[4][4], rb[4][4];
            #pragma unroll
            for (int mf = 0; mf < 4; mf++)
                ldmx4(ra[mf], ab + SWZ((uint32_t)((warp_m * 64 + mf * 16 + lrow) * 128
                                                  + ks * 32 + lkb)));
            #pragma unroll
            for (int j = 0; j < 4; j++)
                ldmx4(rb[j], bb + SWZ((uint32_t)((warp_n * 64 + j * 16 + lrow) * 128
                                                 + ks * 32 + lkb)));
            #pragma unroll
            for (int mf = 0; mf < 4; mf++)
                #pragma unroll
                for (int nf = 0; nf < 8; nf++)
                    mma16816(c[mf][nf], ra[mf],
                             rb[nf >> 1][nf & 1], rb[nf >> 1][(nf & 1) + 2]);
        }
    }

    // -------- epilogue: regs + bias -> gmem --------
    const int tq = lane >> 2, t4 = lane & 3;
    float2 bv[8];
    #pragma unroll
    for (int nf = 0; nf < 8; nf++)
        bv[nf] = *(const float2*)(bias + bn + warp_n * 64 + nf * 8 + t4 * 2);

    #pragma unroll
    for (int mf = 0; mf < 4; mf++) {
        const int r0 = bm + warp_m * 64 + mf * 16 + tq;
        float* o0 = out + (size_t)r0 * N_OUT + bn + warp_n * 64;
        float* o1 = o0 + 8 * N_OUT;
        #pragma unroll
        for (int nf = 0; nf < 8; nf++) {
            const int colo = nf * 8 + t4 * 2;
            *(float2*)(o0 + colo) = make_float2(c[mf][nf][0] + bv[nf].x,
                                                c[mf][nf][1] + bv[nf].y);
            *(float2*)(o1 + colo) = make_float2(c[mf][nf][2] + bv[nf].x,
                                                c[mf][nf][3] + bv[nf].y);
        }
    }
}

// -------------------- launch --------------------
extern "C" void kernel_launch(void* const* d_in, const int* in_sizes, int n_in,
                              void* d_out, int out_size)
{
    (void)in_sizes; (void)n_in; (void)out_size;
    const float* x     = (const float*)d_in[0];
    const float* W     = (const float*)d_in[1];
    const float* bias  = (const float*)d_in[2];
    const float* loraB = (const float*)d_in[3];
    const float* loraA = (const float*)d_in[4];
    const float* scale = (const float*)d_in[5];
    float* out = (float*)d_out;

    pack_x<<<(int)((size_t)M_TOK * K_IN / 1024), 256>>>(x);
    pack_w<<<(int)((size_t)N_OUT * K_IN / 1024), 256>>>(W, loraB, loraA, scale);

    cudaFuncSetAttribute(lora_mma_gemm,
                         cudaFuncAttributeMaxDynamicSharedMemorySize, SMEM_TOTAL);
    lora_mma_gemm<<<GRID_M * GRID_N, 256, SMEM_TOTAL>>>(bias, out);
}